// round 4
// baseline (speedup 1.0000x reference)
#include <cuda_runtime.h>

// EuclideanLoss: loss = mean_n [ w_n * mean_b ||x[b,n,:] - y[b,:,n]||_2 ]
//   x: [B=32, N=8192, D=64] f32   (d_in[0])
//   y: [B=32, D=64, N=8192] f32   (d_in[1])
//   w_n = 1.5 for n in {1,2}, else 1.0
//
// R4: x is staged through shared memory. Previously each thread read its own
// 256B x-row directly (LDG.128 with 256B lane stride -> 32 lines per warp
// request -> ~512 L1 wavefronts per warp-tile; ncu showed L1=54% with DRAM
// stuck at 60%). Now the block loads its 256x64 x-tile coalesced (contiguous
// 128B segments) in two 32KB halves, and per-row reads hit swizzled SMEM
// (conflict-free). y path unchanged (consecutive threads = consecutive n =
// perfect coalescing). 32KB static smem + launch_bounds(256,7) -> 7 CTA/SM,
// grid 1024 fits in one wave (148*7=1036).

#define B_DIM 32
#define N_DIM 8192
#define D_DIM 64
#define THREADS 256
#define NBLK ((B_DIM * N_DIM) / THREADS)   // 1024 blocks, 32 per b (never crosses b)

__device__ float g_partials[NBLK];
__device__ unsigned int g_count = 0;       // re-armed by the finishing block

__global__ __launch_bounds__(THREADS, 7)
void euclid_fused_kernel(const float* __restrict__ x, const float* __restrict__ y,
                         float* __restrict__ out) {
    // 256 rows x 8 float4 (= 32 d-values) per half: 32 KB
    __shared__ float4 sx[THREADS * 8];

    const int tid = threadIdx.x;
    const int t = blockIdx.x * THREADS + tid;   // 0 .. B*N-1
    const int b = t >> 13;                      // t / N_DIM
    const int n = t & (N_DIM - 1);              // t % N_DIM

    const float4* __restrict__ x4 = reinterpret_cast<const float4*>(x);
    const size_t xbase4 = (size_t)blockIdx.x * THREADS * (D_DIM / 4); // block's first row, float4 units
    const float* __restrict__ yp = y + (size_t)b * D_DIM * N_DIM + n;

    float acc = 0.0f;

#pragma unroll
    for (int h = 0; h < 2; ++h) {               // d-halves: [0,32), [32,64)
        // ---- coalesced load of 256 rows x 8 float4 into swizzled smem ----
        // linear li = i*256+tid; row r = li>>3, col c = li&7.
        // Warp request = 32 consecutive li = 4 contiguous 128B segments.
#pragma unroll
        for (int i = 0; i < 8; ++i) {
            int li = i * THREADS + tid;
            int r = li >> 3;
            int c = li & 7;
            float4 v = x4[xbase4 + (size_t)r * (D_DIM / 4) + h * 8 + c];
            sx[r * 8 + ((c + r) & 7)] = v;      // XOR swizzle: conflict-free
        }
        __syncthreads();

        // ---- compute: row tid from smem, y column direct (coalesced) ----
#pragma unroll
        for (int c = 0; c < 8; ++c) {
            float4 xv = sx[tid * 8 + ((c + tid) & 7)];   // logical col c of row tid
            const float* yq = yp + (size_t)(h * 32 + 4 * c) * N_DIM;
            float y0 = yq[0];
            float y1 = yq[(size_t)N_DIM];
            float y2 = yq[(size_t)2 * N_DIM];
            float y3 = yq[(size_t)3 * N_DIM];
            float d0 = xv.x - y0;
            float d1 = xv.y - y1;
            float d2 = xv.z - y2;
            float d3 = xv.w - y3;
            acc = fmaf(d0, d0, acc);
            acc = fmaf(d1, d1, acc);
            acc = fmaf(d2, d2, acc);
            acc = fmaf(d3, d3, acc);
        }
        if (h == 0) __syncthreads();            // protect smem reuse for half 1
    }

    float v = sqrtf(acc);
    if ((unsigned)(n - 1) < 2u) v *= 1.5f;      // n == 1 || n == 2

    // ---- deterministic block reduction ----
#pragma unroll
    for (int off = 16; off > 0; off >>= 1)
        v += __shfl_down_sync(0xffffffffu, v, off);

    __shared__ float s_warp[THREADS / 32];
    __shared__ bool s_is_last;
    if ((tid & 31) == 0) s_warp[tid >> 5] = v;
    __syncthreads();

    if (tid < THREADS / 32) {   // first 8 lanes
        v = s_warp[tid];
#pragma unroll
        for (int off = (THREADS / 64); off > 0; off >>= 1)
            v += __shfl_down_sync(0x000000ffu, v, off);
        if (tid == 0) {
            g_partials[blockIdx.x] = v;
            __threadfence();                       // make partial visible
            unsigned int prev = atomicAdd(&g_count, 1u);
            s_is_last = (prev == NBLK - 1);
        }
    }
    __syncthreads();

    if (!s_is_last) return;

    // ---- finishing block: reduce 1024 partials in FIXED order (bit-stable) ----
    __threadfence();
    float s = g_partials[tid]
            + g_partials[tid + 256]
            + g_partials[tid + 512]
            + g_partials[tid + 768];

#pragma unroll
    for (int off = 16; off > 0; off >>= 1)
        s += __shfl_down_sync(0xffffffffu, s, off);

    if ((tid & 31) == 0) s_warp[tid >> 5] = s;
    __syncthreads();

    if (tid < THREADS / 32) {
        s = s_warp[tid];
#pragma unroll
        for (int off = (THREADS / 64); off > 0; off >>= 1)
            s += __shfl_down_sync(0x000000ffu, s, off);
        if (tid == 0) {
            out[0] = s * (1.0f / ((float)B_DIM * (float)N_DIM));
            g_count = 0;   // re-arm for the next graph replay
        }
    }
}

extern "C" void kernel_launch(void* const* d_in, const int* in_sizes, int n_in,
                              void* d_out, int out_size) {
    const float* x = (const float*)d_in[0];
    const float* y = (const float*)d_in[1];
    float* out = (float*)d_out;

    euclid_fused_kernel<<<NBLK, THREADS>>>(x, y, out);
}

// round 5
// speedup vs baseline: 1.9170x; 1.9170x over previous
#include <cuda_runtime.h>

// EuclideanLoss: loss = mean_n [ w_n * mean_b ||x[b,n,:] - y[b,:,n]||_2 ]
//   x: [B=32, N=8192, D=64] f32   (d_in[0])
//   y: [B=32, D=64, N=8192] f32   (d_in[1])
//   w_n = 1.5 for n in {1,2}, else 1.0
//
// R5: R3 structure (direct loads, fused last-block reduction) but each thread
// now owns TWO rows (t and t+131072) with interleaved loads and independent
// accumulators. R3 was MLP-limited: regs=32 allowed only ~15KB/SM in flight
// vs the ~27KB needed to saturate HBM (DRAM=60.5%). Two independent chains
// per thread ~doubles in-flight bytes; higher reg use still yields >=32
// warps/SM. No barriers in the hot loop (R4 lesson: phase barriers expose
// DRAM latency serially -> 2x regression).

#define B_DIM 32
#define N_DIM 8192
#define D_DIM 64
#define THREADS 256
#define ROWS (B_DIM * N_DIM)               // 262144
#define HALF (ROWS / 2)                    // 131072
#define NBLK (HALF / THREADS)              // 512 blocks

__device__ float g_partials[NBLK];
__device__ unsigned int g_count = 0;       // re-armed by the finishing block

__global__ __launch_bounds__(THREADS)
void euclid_fused_kernel(const float* __restrict__ x, const float* __restrict__ y,
                         float* __restrict__ out) {
    const int tid = threadIdx.x;
    const int r0 = blockIdx.x * THREADS + tid;   // row 0: 0 .. HALF-1
    const int r1 = r0 + HALF;                    // row 1: second half
    const int b0 = r0 >> 13;                     // r0 / N_DIM
    const int n  = r0 & (N_DIM - 1);             // same n for both rows
    const int b1 = b0 + (HALF >> 13);            // = b0 + 16

    // x rows: contiguous 64 floats each, 16x LDG.128 per row
    const float4* __restrict__ xa =
        reinterpret_cast<const float4*>(x + ((size_t)b0 * N_DIM + n) * D_DIM);
    const float4* __restrict__ xb =
        reinterpret_cast<const float4*>(x + ((size_t)b1 * N_DIM + n) * D_DIM);
    // y columns: consecutive threads -> consecutive n => perfectly coalesced
    const float* __restrict__ ya = y + (size_t)b0 * D_DIM * N_DIM + n;
    const float* __restrict__ yb = y + (size_t)b1 * D_DIM * N_DIM + n;

    float acc0 = 0.0f, acc1 = 0.0f;
#pragma unroll
    for (int i = 0; i < D_DIM / 4; ++i) {
        float4 va = xa[i];
        float4 vb = xb[i];
        float a0 = ya[(size_t)(4 * i + 0) * N_DIM];
        float a1 = ya[(size_t)(4 * i + 1) * N_DIM];
        float a2 = ya[(size_t)(4 * i + 2) * N_DIM];
        float a3 = ya[(size_t)(4 * i + 3) * N_DIM];
        float b0v = yb[(size_t)(4 * i + 0) * N_DIM];
        float b1v = yb[(size_t)(4 * i + 1) * N_DIM];
        float b2v = yb[(size_t)(4 * i + 2) * N_DIM];
        float b3v = yb[(size_t)(4 * i + 3) * N_DIM];

        float d;
        d = va.x - a0;  acc0 = fmaf(d, d, acc0);
        d = va.y - a1;  acc0 = fmaf(d, d, acc0);
        d = va.z - a2;  acc0 = fmaf(d, d, acc0);
        d = va.w - a3;  acc0 = fmaf(d, d, acc0);
        d = vb.x - b0v; acc1 = fmaf(d, d, acc1);
        d = vb.y - b1v; acc1 = fmaf(d, d, acc1);
        d = vb.z - b2v; acc1 = fmaf(d, d, acc1);
        d = vb.w - b3v; acc1 = fmaf(d, d, acc1);
    }

    float v = sqrtf(acc0) + sqrtf(acc1);
    if ((unsigned)(n - 1) < 2u) v *= 1.5f;       // n == 1 || n == 2 (same n both rows)

    // ---- deterministic block reduction ----
#pragma unroll
    for (int off = 16; off > 0; off >>= 1)
        v += __shfl_down_sync(0xffffffffu, v, off);

    __shared__ float s_warp[THREADS / 32];
    __shared__ bool s_is_last;
    if ((tid & 31) == 0) s_warp[tid >> 5] = v;
    __syncthreads();

    if (tid < THREADS / 32) {   // first 8 lanes
        v = s_warp[tid];
#pragma unroll
        for (int off = (THREADS / 64); off > 0; off >>= 1)
            v += __shfl_down_sync(0x000000ffu, v, off);
        if (tid == 0) {
            g_partials[blockIdx.x] = v;
            __threadfence();                       // make partial visible
            unsigned int prev = atomicAdd(&g_count, 1u);
            s_is_last = (prev == NBLK - 1);
        }
    }
    __syncthreads();

    if (!s_is_last) return;

    // ---- finishing block: reduce 512 partials in FIXED order (bit-stable) ----
    __threadfence();
    float s = g_partials[tid] + g_partials[tid + 256];

#pragma unroll
    for (int off = 16; off > 0; off >>= 1)
        s += __shfl_down_sync(0xffffffffu, s, off);

    if ((tid & 31) == 0) s_warp[tid >> 5] = s;
    __syncthreads();

    if (tid < THREADS / 32) {
        s = s_warp[tid];
#pragma unroll
        for (int off = (THREADS / 64); off > 0; off >>= 1)
            s += __shfl_down_sync(0x000000ffu, s, off);
        if (tid == 0) {
            out[0] = s * (1.0f / ((float)B_DIM * (float)N_DIM));
            g_count = 0;   // re-arm for the next graph replay
        }
    }
}

extern "C" void kernel_launch(void* const* d_in, const int* in_sizes, int n_in,
                              void* d_out, int out_size) {
    const float* x = (const float*)d_in[0];
    const float* y = (const float*)d_in[1];
    float* out = (float*)d_out;

    euclid_fused_kernel<<<NBLK, THREADS>>>(x, y, out);
}

// round 6
// speedup vs baseline: 2.0359x; 1.0620x over previous
#include <cuda_runtime.h>

// EuclideanLoss: loss = mean_n [ w_n * mean_b ||x[b,n,:] - y[b,:,n]||_2 ]
//   x: [B=32, N=8192, D=64] f32   (d_in[0])
//   y: [B=32, D=64, N=8192] f32   (d_in[1])
//   w_n = 1.5 for n in {1,2}, else 1.0
//
// R6: R3 shape (1 row/thread, grid 1024x256, direct loads, fused last-block
// reduction) + forced MLP. R3/R5 showed the binder is in-flight bytes: ptxas
// capped regs at 32 and only kept ~2-4 loads outstanding per warp (DRAM 60%).
// Fix: explicitly batch 8x LDG.128 of the x row into a live register array
// before consuming (MLP_p1=8), with launch_bounds(256,4) raising the reg
// ceiling to 64 while guaranteeing 4 CTAs/SM (32 warps). In-flight/SM ~130KB
// >> ~27KB needed to cover DRAM latency. y path unchanged (perfectly
// coalesced). No barriers in the hot loop (R4 lesson).

#define B_DIM 32
#define N_DIM 8192
#define D_DIM 64
#define THREADS 256
#define NBLK ((B_DIM * N_DIM) / THREADS)   // 1024 blocks

__device__ float g_partials[NBLK];
__device__ unsigned int g_count = 0;       // re-armed by the finishing block

__global__ __launch_bounds__(THREADS, 4)
void euclid_fused_kernel(const float* __restrict__ x, const float* __restrict__ y,
                         float* __restrict__ out) {
    const int tid = threadIdx.x;
    const int t = blockIdx.x * THREADS + tid;   // 0 .. B*N-1
    const int b = t >> 13;                      // t / N_DIM
    const int n = t & (N_DIM - 1);              // t % N_DIM

    const float4* __restrict__ xp =
        reinterpret_cast<const float4*>(x + ((size_t)b * N_DIM + n) * D_DIM);
    // y column: consecutive threads -> consecutive n => each (b,d) warp load
    // is one perfectly coalesced 128B transaction.
    const float* __restrict__ yp = y + (size_t)b * D_DIM * N_DIM + n;

    float acc0 = 0.0f, acc1 = 0.0f;

#pragma unroll
    for (int h = 0; h < 2; ++h) {               // d-halves [0,32) and [32,64)
        // ---- front-batched x loads: 8 independent LDG.128 in flight ----
        float4 xv[8];
#pragma unroll
        for (int i = 0; i < 8; ++i)
            xv[i] = xp[h * 8 + i];

        // ---- y loads (coalesced) + FMA consume ----
#pragma unroll
        for (int i = 0; i < 8; ++i) {
            const float* yq = yp + (size_t)(h * 32 + 4 * i) * N_DIM;
            float y0 = yq[0];
            float y1 = yq[(size_t)N_DIM];
            float y2 = yq[(size_t)2 * N_DIM];
            float y3 = yq[(size_t)3 * N_DIM];
            float d;
            d = xv[i].x - y0; acc0 = fmaf(d, d, acc0);
            d = xv[i].y - y1; acc1 = fmaf(d, d, acc1);
            d = xv[i].z - y2; acc0 = fmaf(d, d, acc0);
            d = xv[i].w - y3; acc1 = fmaf(d, d, acc1);
        }
    }

    float v = sqrtf(acc0 + acc1);
    if ((unsigned)(n - 1) < 2u) v *= 1.5f;      // n == 1 || n == 2

    // ---- deterministic block reduction ----
#pragma unroll
    for (int off = 16; off > 0; off >>= 1)
        v += __shfl_down_sync(0xffffffffu, v, off);

    __shared__ float s_warp[THREADS / 32];
    __shared__ bool s_is_last;
    if ((tid & 31) == 0) s_warp[tid >> 5] = v;
    __syncthreads();

    if (tid < THREADS / 32) {   // first 8 lanes
        v = s_warp[tid];
#pragma unroll
        for (int off = (THREADS / 64); off > 0; off >>= 1)
            v += __shfl_down_sync(0x000000ffu, v, off);
        if (tid == 0) {
            g_partials[blockIdx.x] = v;
            __threadfence();                       // make partial visible
            unsigned int prev = atomicAdd(&g_count, 1u);
            s_is_last = (prev == NBLK - 1);
        }
    }
    __syncthreads();

    if (!s_is_last) return;

    // ---- finishing block: reduce 1024 partials in FIXED order (bit-stable) ----
    __threadfence();
    float s = g_partials[tid]
            + g_partials[tid + 256]
            + g_partials[tid + 512]
            + g_partials[tid + 768];

#pragma unroll
    for (int off = 16; off > 0; off >>= 1)
        s += __shfl_down_sync(0xffffffffu, s, off);

    if ((tid & 31) == 0) s_warp[tid >> 5] = s;
    __syncthreads();

    if (tid < THREADS / 32) {
        s = s_warp[tid];
#pragma unroll
        for (int off = (THREADS / 64); off > 0; off >>= 1)
            s += __shfl_down_sync(0x000000ffu, s, off);
        if (tid == 0) {
            out[0] = s * (1.0f / ((float)B_DIM * (float)N_DIM));
            g_count = 0;   // re-arm for the next graph replay
        }
    }
}

extern "C" void kernel_launch(void* const* d_in, const int* in_sizes, int n_in,
                              void* d_out, int out_size) {
    const float* x = (const float*)d_in[0];
    const float* y = (const float*)d_in[1];
    float* out = (float*)d_out;

    euclid_fused_kernel<<<NBLK, THREADS>>>(x, y, out);
}